// round 15
// baseline (speedup 1.0000x reference)
#include <cuda_runtime.h>
#include <cuda_bf16.h>
#include <stdint.h>

// Problem constants (match reference)
#define NSEG   8
#define KPTS   768
#define NPTS   10
#define NMAPS  7            // NSEG - SEG_DIST
#define WIMG   1024
#define KK     (KPTS * KPTS)          // 589824
#define STOT   (NMAPS * KK)           // 4128768  (each of 4 output rows)
#define PLANE  (WIMG * WIMG)          // 1048576

#define EP_BLOCKS 42                  // 2*NMAPS*KPTS / 256
#define TPB_MAP   1024                // (PLANE/4)/256 transpose blocks per map (4 px/thread)
#define T_ALL     (NMAPS * TPB_MAP)   // 7168
#define PROD      (EP_BLOCKS + T_ALL) // 7210 producer bids (all BEFORE consumers)
#define W_ALL     (STOT / 256)        // 16128 weight blocks
#define GRID_ALL  (PROD + W_ALL)      // 23338

// PAF transposed to channel-interleaved (m, y, x, {c0,c1}): one 8B load fetches
// both channels of a sample point (halves scattered L1tex wavefronts — the
// binding resource of the whole problem).
__device__ float2 g_pafi[NMAPS * PLANE];     // 56 MB static scratch

// Endpoint samples (hoisted p=0 / p=9 gathers — depend on a single endpoint).
__device__ float2 g_e0[NMAPS * KPTS];
__device__ float2 g_e9[NMAPS * KPTS];

// Readiness flags, re-zeroed each launch by init_kernel (the separate tiny
// launch measured faster overall than per-block self-clean atomics: 154.0 vs
// 155.6 — 16k same-address tail atomics are partially exposed).
__device__ int g_tctr[NMAPS];
__device__ int g_ectr;

__global__ void init_kernel() {
    if (threadIdx.x < NMAPS) g_tctr[threadIdx.x] = 0;
    if (threadIdx.x == NMAPS) g_ectr = 0;
}

// Acquire load pairing with producer __threadfence + atomicAdd. The "memory"
// clobber also stops the compiler hoisting the (readonly-annotated) __ldg data
// loads above the wait — the exact mechanism of the R6 staleness bug.
__device__ __forceinline__ int ld_acquire(const int* p) {
    int v;
    asm volatile("ld.acquire.gpu.s32 %0, [%1];" : "=r"(v) : "l"(p) : "memory");
    return v;
}

// ---------------------------------------------------------------------------
// Mega kernel, producers-FIRST fixed layout (proven fastest structure; the win
// is merged launch gap + merged tails — overlap attempts all lost to shared L2):
//   [0,42)           endpoint precompute
//   [42,7210)        transpose, map-major (4 px/thread — measured optimum; 8/16
//                    px variants regressed twice: producer phase is bound by
//                    the L2 store/fill path, not load latency)
//   [7210,23338)     weight pairs, map-major
// Producers never wait and precede all consumers in launch order -> no deadlock.
// Weight phase uses __ldg (LDG.NC): measured ~8us faster than coherent LDG for
// the scattered gathers; safe because all producer blocks retire waves before
// any weight(m) block is scheduled + L1D is flushed per launch + acquire wait.
__global__ void __launch_bounds__(256) mega_kernel(
    const int* __restrict__ sk,      // skeletons (NSEG*KPTS, 3) int32 [seg,x,y]
    const float* __restrict__ paf,   // (NMAPS, 2, W, H) float32
    float* __restrict__ out)         // [i1 | i2 | li | R], each STOT floats
{
    unsigned bid = blockIdx.x;

    // ---- endpoint producers ----
    if (bid < EP_BLOCKS) {
        int t = bid * 256 + threadIdx.x;                 // over 2*NMAPS*KPTS
        int which = t / (NMAPS * KPTS);                  // 0 -> E0, 1 -> E9
        int r = t - which * (NMAPS * KPTS);
        int m = r / KPTS;
        int q = r - m * KPTS;
        int base = ((m + which) * KPTS + q) * 3;         // E0: seg m; E9: seg m+1
        int x = __ldg(sk + base + 1);
        int y = __ldg(sk + base + 2);
        const float* pm = paf + (size_t)m * 2 * PLANE;
        float c0 = __ldg(pm + y * WIMG + x);
        float c1 = __ldg(pm + PLANE + y * WIMG + x);
        (which ? g_e9 : g_e0)[r] = make_float2(c0, c1);
        __threadfence();
        __syncthreads();
        if (threadIdx.x == 0) atomicAdd(&g_ectr, 1);
        return;
    }

    // ---- transpose producers: (c,y,x) -> (y,x,{c0,c1}), 4 px/thread ----
    if (bid < PROD) {
        unsigned tb = bid - EP_BLOCKS;
        int m  = tb / TPB_MAP;
        int r4 = (tb - m * TPB_MAP) * 256 + threadIdx.x;
        const float4* c0p = (const float4*)(paf + (size_t)m * 2 * PLANE);
        const float4* c1p = (const float4*)(paf + (size_t)m * 2 * PLANE + PLANE);
        float4 c0 = __ldg(c0p + r4);
        float4 c1 = __ldg(c1p + r4);
        float4* dst = (float4*)&g_pafi[(size_t)m * PLANE + 4 * r4];
        dst[0] = make_float4(c0.x, c1.x, c0.y, c1.y);
        dst[1] = make_float4(c0.z, c1.z, c0.w, c1.w);
        __threadfence();
        __syncthreads();
        if (threadIdx.x == 0) atomicAdd(&g_tctr[m], 1);
        return;
    }

    // ---- weight consumers ----
    int idx = (bid - PROD) * 256 + threadIdx.x;   // 0..STOT-1
    int j = idx % KPTS;                 // p1 index (lane-fast, coalesced)
    int t2 = idx / KPTS;
    int i = t2 % KPTS;                  // p2 index (warp-uniform)
    int m = t2 / KPTS;                  // map (block-uniform)

    // Backstop wait (virtually never spins: producers are ~6 waves ahead).
    if (threadIdx.x == 0) {
        while (ld_acquire(&g_tctr[m]) < TPB_MAP || ld_acquire(&g_ectr) < EP_BLOCKS)
            __nanosleep(100);
    }
    __syncthreads();   // broadcasts the acquire ordering to the block

    int b1 = (m * KPTS + j) * 3;
    int b2 = ((m + 1) * KPTS + i) * 3;
    int x1 = __ldg(sk + b1 + 1);
    int y1 = __ldg(sk + b1 + 2);
    int x2 = __ldg(sk + b2 + 1);
    int y2 = __ldg(sk + b2 + 2);

    const float2* __restrict__ pafm = g_pafi + (size_t)m * PLANE;

    float2 e0 = __ldg(&g_e0[m * KPTS + j]);   // coalesced
    float2 e9 = __ldg(&g_e9[m * KPTS + i]);   // broadcast
    float s0 = e0.x + e9.x;
    float s1 = e0.y + e9.y;

#pragma unroll
    for (int p = 1; p < NPTS - 1; p++) {
        // integer floor-div by 9; operands nonnegative so C '/' == floor
        int lx = (x1 * (NPTS - 1 - p) + x2 * p) / (NPTS - 1);
        int ly = (y1 * (NPTS - 1 - p) + y2 * p) / (NPTS - 1);
        float2 v = __ldg(&pafm[ly * WIMG + lx]);
        s0 += v.x;
        s1 += v.y;
    }

    float dx = (float)(x2 - x1);
    float dy = (float)(y2 - y1);
    float R2 = dx * dx + dy * dy;
    float R  = sqrtf(R2);
    // li = mean_p sum_c (tv_c/R)*paf_c = (dx*s0 + dy*s1)/(R*NPTS); NaN (R==0) -> 0
    float li = (R2 > 0.f) ? (dx * s0 + dy * s1) / (R * (float)NPTS) : 0.f;

    // Streaming stores: don't evict the L2-resident PAF with the 66MB output.
    __stcs(&out[idx],            (float)(m * KPTS + j));       // edges_indices[0]
    __stcs(&out[STOT + idx],     (float)((m + 1) * KPTS + i)); // edges_indices[1]
    __stcs(&out[2 * STOT + idx], li);                          // edges_costs[0]
    __stcs(&out[3 * STOT + idx], R);                           // edges_costs[1]
}

extern "C" void kernel_launch(void* const* d_in, const int* in_sizes, int n_in,
                              void* d_out, int out_size) {
    const int*   sk  = (const int*)d_in[0];     // skeletons (6144, 3) int32
    const float* paf = (const float*)d_in[1];   // PAF (7, 2, 1024, 1024) float32
    float* out = (float*)d_out;

    init_kernel<<<1, 32>>>();
    mega_kernel<<<GRID_ALL, 256>>>(sk, paf, out);
}

// round 16
// speedup vs baseline: 1.0133x; 1.0133x over previous
#include <cuda_runtime.h>
#include <cuda_bf16.h>
#include <stdint.h>

// Problem constants (match reference)
#define NSEG   8
#define KPTS   768
#define NPTS   10
#define NMAPS  7            // NSEG - SEG_DIST
#define WIMG   1024
#define KK     (KPTS * KPTS)          // 589824
#define STOT   (NMAPS * KK)           // 4128768  (each of 4 output rows)
#define PLANE  (WIMG * WIMG)          // 1048576

#define EP_BLOCKS ((2 * NMAPS * KPTS + 255) / 256)   // 42 endpoint blocks
#define TPB_MAP   1024                // (PLANE/4)/256 transpose blocks per map
#define T_ALL     (NMAPS * TPB_MAP)   // 7168
#define W_ALL     (STOT / 256)        // 16128 weight blocks

// PAF transposed to channel-interleaved (m, y, x, {c0,c1}): one 8B load fetches
// both channels of a sample point (halves scattered L1tex wavefronts — the
// binding resource of the whole problem).
__device__ float2 g_pafi[NMAPS * PLANE];     // 56 MB static scratch

// Endpoint samples (hoisted p=0 / p=9 gathers — depend on a single endpoint).
__device__ float2 g_e0[NMAPS * KPTS];
__device__ float2 g_e9[NMAPS * KPTS];

// Readiness counters (re-zeroed each launch by init_kernel).
__device__ int g_tctr[NMAPS];
__device__ int g_ectr;

// ---------------------------------------------------------------------------
__global__ void init_kernel() {
    if (threadIdx.x < NMAPS) g_tctr[threadIdx.x] = 0;
    if (threadIdx.x == NMAPS) g_ectr = 0;
}

// ---------------------------------------------------------------------------
// Mega kernel. Block roles by blockIdx (producers first => no deadlock: they
// fill the first waves and never wait, consumers only get slots as they retire):
//   [0, EP_BLOCKS)                    endpoint precompute (original layout)
//   [EP_BLOCKS, EP_BLOCKS+T_ALL)      transpose, map-ordered (map 0 first)
//   [EP_BLOCKS+T_ALL, ... +W_ALL)     weight pairs, map-ordered
// The single launch merges the inter-kernel gap and shares one tail — measured
// fastest total (154.0us) across all structural variants. Weight phase uses
// __ldg (LDG.NC, ~8us faster than coherent LDG for the scattered gathers);
// safe because all producer blocks retire waves before any weight(m) block is
// scheduled and L1D is flushed per launch. The atomicAdd(ptr,0) backstop poll
// (no asm memory clobber) leaves the compiler free to pre-schedule the 8-deep
// independent gather batch after the __syncthreads.
__global__ void __launch_bounds__(256) mega_kernel(
    const int* __restrict__ sk,      // skeletons (NSEG*KPTS, 3) int32 [seg,x,y]
    const float* __restrict__ paf,   // (NMAPS, 2, W, H) float32
    float* __restrict__ out)         // [i1 | i2 | li | R], each STOT floats
{
    unsigned bid = blockIdx.x;

    // ---- endpoint producer ----
    if (bid < EP_BLOCKS) {
        int t = bid * 256 + threadIdx.x;                 // over 2*NMAPS*KPTS
        if (t < 2 * NMAPS * KPTS) {
            int which = t / (NMAPS * KPTS);              // 0 -> E0, 1 -> E9
            int r = t - which * (NMAPS * KPTS);
            int m = r / KPTS;
            int q = r - m * KPTS;
            int base = ((m + which) * KPTS + q) * 3;     // E0: seg m; E9: seg m+1
            int x = __ldg(sk + base + 1);
            int y = __ldg(sk + base + 2);
            const float* pm = paf + (size_t)m * 2 * PLANE;
            float c0 = __ldg(pm + y * WIMG + x);
            float c1 = __ldg(pm + PLANE + y * WIMG + x);
            (which ? g_e9 : g_e0)[r] = make_float2(c0, c1);
        }
        __threadfence();
        __syncthreads();
        if (threadIdx.x == 0) atomicAdd(&g_ectr, 1);
        return;
    }

    // ---- transpose producer: (c,y,x) -> (y,x,{c0,c1}), 4 px/thread ----
    if (bid < EP_BLOCKS + T_ALL) {
        unsigned tb = bid - EP_BLOCKS;
        int m  = tb / TPB_MAP;
        int r4 = (tb - m * TPB_MAP) * 256 + threadIdx.x;
        const float4* c0p = (const float4*)(paf + (size_t)m * 2 * PLANE);
        const float4* c1p = (const float4*)(paf + (size_t)m * 2 * PLANE + PLANE);
        float4 c0 = __ldg(c0p + r4);
        float4 c1 = __ldg(c1p + r4);
        float4* dst = (float4*)&g_pafi[(size_t)m * PLANE + 4 * r4];
        dst[0] = make_float4(c0.x, c1.x, c0.y, c1.y);
        dst[1] = make_float4(c0.z, c1.z, c0.w, c1.w);
        __threadfence();
        __syncthreads();
        if (threadIdx.x == 0) atomicAdd(&g_tctr[m], 1);
        return;
    }

    // ---- weight consumer ----
    int local = (bid - EP_BLOCKS - T_ALL) * 256 + threadIdx.x;  // 0..STOT-1
    int j = local % KPTS;              // p1 index (lane-fast, coalesced)
    int t2 = local / KPTS;
    int i = t2 % KPTS;                 // p2 index (warp-uniform)
    int m = t2 / KPTS;                 // map (block-uniform)

    // Backstop wait: transpose(m) + endpoints are ~6 waves ahead, so this
    // essentially never spins (tid 0 polls).
    if (threadIdx.x == 0) {
        while (atomicAdd(&g_tctr[m], 0) < TPB_MAP || atomicAdd(&g_ectr, 0) < EP_BLOCKS)
            __nanosleep(200);
    }
    __syncthreads();

    int b1 = (m * KPTS + j) * 3;
    int b2 = ((m + 1) * KPTS + i) * 3;
    int x1 = __ldg(sk + b1 + 1);
    int y1 = __ldg(sk + b1 + 2);
    int x2 = __ldg(sk + b2 + 1);
    int y2 = __ldg(sk + b2 + 2);

    const float2* __restrict__ pafm = g_pafi + (size_t)m * PLANE;

    float2 e0 = __ldg(&g_e0[m * KPTS + j]);   // coalesced
    float2 e9 = __ldg(&g_e9[m * KPTS + i]);   // broadcast
    float s0 = e0.x + e9.x;
    float s1 = e0.y + e9.y;

#pragma unroll
    for (int p = 1; p < NPTS - 1; p++) {
        // integer floor-div by 9; operands nonnegative so C '/' == floor
        int lx = (x1 * (NPTS - 1 - p) + x2 * p) / (NPTS - 1);
        int ly = (y1 * (NPTS - 1 - p) + y2 * p) / (NPTS - 1);
        float2 v = __ldg(&pafm[ly * WIMG + lx]);
        s0 += v.x;
        s1 += v.y;
    }

    float dx = (float)(x2 - x1);
    float dy = (float)(y2 - y1);
    float R2 = dx * dx + dy * dy;
    float R  = sqrtf(R2);
    // li = mean_p sum_c (tv_c/R)*paf_c = (dx*s0 + dy*s1)/(R*NPTS); NaN (R==0) -> 0
    float li = (R2 > 0.f) ? (dx * s0 + dy * s1) / (R * (float)NPTS) : 0.f;

    int idx = m * KK + i * KPTS + j;
    // Streaming stores: don't evict the L2-resident PAF with the 66MB output.
    __stcs(&out[idx],            (float)(m * KPTS + j));       // edges_indices[0]
    __stcs(&out[STOT + idx],     (float)((m + 1) * KPTS + i)); // edges_indices[1]
    __stcs(&out[2 * STOT + idx], li);                          // edges_costs[0]
    __stcs(&out[3 * STOT + idx], R);                           // edges_costs[1]
}

extern "C" void kernel_launch(void* const* d_in, const int* in_sizes, int n_in,
                              void* d_out, int out_size) {
    const int*   sk  = (const int*)d_in[0];     // skeletons (6144, 3) int32
    const float* paf = (const float*)d_in[1];   // PAF (7, 2, 1024, 1024) float32
    float* out = (float*)d_out;

    init_kernel<<<1, 32>>>();
    mega_kernel<<<EP_BLOCKS + T_ALL + W_ALL, 256>>>(sk, paf, out);
}